// round 4
// baseline (speedup 1.0000x reference)
#include <cuda_runtime.h>
#include <cuda_bf16.h>

#define NUM_AA 20
#define FEAT_DIM 16
#define LUT_SIZE (NUM_AA * NUM_AA)

// Scratch for the 400-entry tanh(delta^T M delta) lookup table.
// (No device allocation allowed; __device__ global is the sanctioned scratch.)
__device__ float g_lut[LUT_SIZE];

// ---------------------------------------------------------------------------
// Kernel 1: build the 20x20 LUT. One thread per (i, j) entry. Trivial cost.
// ---------------------------------------------------------------------------
__global__ void snack_build_lut(const float* __restrict__ features,
                                const float* __restrict__ M) {
    int t = blockIdx.x * blockDim.x + threadIdx.x;
    if (t >= LUT_SIZE) return;
    int i = t / NUM_AA;
    int j = t % NUM_AA;

    float delta[FEAT_DIM];
#pragma unroll
    for (int d = 0; d < FEAT_DIM; d++)
        delta[d] = features[i * FEAT_DIM + d] - features[j * FEAT_DIM + d];

    float dist = 0.0f;
#pragma unroll
    for (int d = 0; d < FEAT_DIM; d++) {
        float md = 0.0f;
#pragma unroll
        for (int e = 0; e < FEAT_DIM; e++)
            md = fmaf(M[d * FEAT_DIM + e], delta[e], md);
        dist = fmaf(delta[d], md, dist);
    }
    g_lut[t] = tanhf(dist);
}

// ---------------------------------------------------------------------------
// Kernel 2: pure gather. 4 pairs per thread via int4/float4 vectorization.
// Traffic: 12 B/pair -> ~100.7 MB total; strictly HBM-bound.
// LUT staged into shared memory (1.6 KB) for low-latency random access.
// ---------------------------------------------------------------------------
__global__ void __launch_bounds__(256)
snack_gather(const int4* __restrict__ idx_i4,
             const int4* __restrict__ idx_j4,
             float4* __restrict__ out4,
             int n4) {
    __shared__ float s_lut[LUT_SIZE];
    for (int k = threadIdx.x; k < LUT_SIZE; k += blockDim.x)
        s_lut[k] = g_lut[k];
    __syncthreads();

    int t = blockIdx.x * blockDim.x + threadIdx.x;
    if (t >= n4) return;

    int4 a = idx_i4[t];
    int4 b = idx_j4[t];

    float4 o;
    o.x = s_lut[a.x * NUM_AA + b.x];
    o.y = s_lut[a.y * NUM_AA + b.y];
    o.z = s_lut[a.z * NUM_AA + b.z];
    o.w = s_lut[a.w * NUM_AA + b.w];

    out4[t] = o;
}

// Tail handler for n not divisible by 4 (defensive; 2^23 is divisible).
__global__ void snack_gather_tail(const int* __restrict__ idx_i,
                                  const int* __restrict__ idx_j,
                                  float* __restrict__ out,
                                  int start, int n) {
    int t = start + blockIdx.x * blockDim.x + threadIdx.x;
    if (t >= n) return;
    out[t] = g_lut[idx_i[t] * NUM_AA + idx_j[t]];
}

extern "C" void kernel_launch(void* const* d_in, const int* in_sizes, int n_in,
                              void* d_out, int out_size) {
    // metadata order mirrors setup_inputs: features, M, idx_i, idx_j
    const float* features = (const float*)d_in[0];
    const float* M        = (const float*)d_in[1];
    const int*   idx_i    = (const int*)d_in[2];
    const int*   idx_j    = (const int*)d_in[3];
    float*       out      = (float*)d_out;

    int n = in_sizes[2];   // NUM_PAIRS

    // Build the 400-entry LUT (2 blocks x 256 threads).
    snack_build_lut<<<(LUT_SIZE + 255) / 256, 256>>>(features, M);

    // Vectorized gather.
    int n4 = n / 4;
    if (n4 > 0) {
        int threads = 256;
        int blocks  = (n4 + threads - 1) / threads;
        snack_gather<<<blocks, threads>>>((const int4*)idx_i,
                                          (const int4*)idx_j,
                                          (float4*)out, n4);
    }

    // Residual elements (none for n = 2^23, but keep it correct for any n).
    int done = n4 * 4;
    int rem  = n - done;
    if (rem > 0) {
        snack_gather_tail<<<(rem + 255) / 256, 256>>>(idx_i, idx_j, out, done, n);
    }
}

// round 7
// speedup vs baseline: 1.1569x; 1.1569x over previous
#include <cuda_runtime.h>
#include <cuda_bf16.h>

#define NUM_AA 20
#define FEAT_DIM 16
#define LUT_SIZE (NUM_AA * NUM_AA)

// ---------------------------------------------------------------------------
// Single fused kernel.
// Per block: build the 400-entry tanh LUT in shared memory using the
// factorization  delta^T M delta = (f_i M - f_j M) . (f_i - f_j),
// then grid-stride gather with x2 unroll for MLP.
// ---------------------------------------------------------------------------
__global__ void __launch_bounds__(256)
snack_fused(const float* __restrict__ features,
            const float* __restrict__ M,
            const int4*  __restrict__ ii4,
            const int4*  __restrict__ jj4,
            float4*      __restrict__ out4,
            int n4,
            const int*   __restrict__ ii,
            const int*   __restrict__ jj,
            float*       __restrict__ out,
            int n)
{
    __shared__ float sF [NUM_AA * FEAT_DIM];   // 320 floats
    __shared__ float sM [FEAT_DIM * FEAT_DIM]; // 256 floats
    __shared__ float sFM[NUM_AA * FEAT_DIM];   // 320 floats: F @ M
    __shared__ float s_lut[LUT_SIZE];          // 400 floats

    const int tid = threadIdx.x;

    // Stage F and M.
    for (int k = tid; k < NUM_AA * FEAT_DIM; k += 256) sF[k] = features[k];
    sM[tid] = M[tid];              // blockDim == 256 == FEAT_DIM^2
    __syncthreads();

    // FM[i][e] = sum_d F[i][d] * M[d][e]   (320 entries, 16 FMA each)
    for (int k = tid; k < NUM_AA * FEAT_DIM; k += 256) {
        int i = k >> 4, e = k & 15;
        float acc = 0.0f;
#pragma unroll
        for (int d = 0; d < FEAT_DIM; d++)
            acc = fmaf(sF[i * FEAT_DIM + d], sM[d * FEAT_DIM + e], acc);
        sFM[k] = acc;
    }
    __syncthreads();

    // lut[i][j] = tanh( sum_e (FM[i][e]-FM[j][e]) * (F[i][e]-F[j][e]) )
    for (int k = tid; k < LUT_SIZE; k += 256) {
        int i = k / NUM_AA, j = k - i * NUM_AA;
        float acc = 0.0f;
#pragma unroll
        for (int e = 0; e < FEAT_DIM; e++) {
            float dm = sFM[i * FEAT_DIM + e] - sFM[j * FEAT_DIM + e];
            float df = sF [i * FEAT_DIM + e] - sF [j * FEAT_DIM + e];
            acc = fmaf(dm, df, acc);
        }
        s_lut[k] = tanhf(acc);
    }
    __syncthreads();

    // ---- Gather: grid-stride, 2 int4 chunks per iteration for MLP ----
    const int stride = gridDim.x * blockDim.x;
    int t0 = blockIdx.x * (blockDim.x * 2) + tid;

    for (; t0 + blockDim.x < n4 || t0 < n4; t0 += stride * 2) {
        int t1 = t0 + blockDim.x;
        bool v0 = t0 < n4;
        bool v1 = t1 < n4;

        int4 a0, b0, a1, b1;
        if (v0) { a0 = ii4[t0]; b0 = jj4[t0]; }
        if (v1) { a1 = ii4[t1]; b1 = jj4[t1]; }

        if (v0) {
            float4 o;
            o.x = s_lut[a0.x * NUM_AA + b0.x];
            o.y = s_lut[a0.y * NUM_AA + b0.y];
            o.z = s_lut[a0.z * NUM_AA + b0.z];
            o.w = s_lut[a0.w * NUM_AA + b0.w];
            out4[t0] = o;
        }
        if (v1) {
            float4 o;
            o.x = s_lut[a1.x * NUM_AA + b1.x];
            o.y = s_lut[a1.y * NUM_AA + b1.y];
            o.z = s_lut[a1.z * NUM_AA + b1.z];
            o.w = s_lut[a1.w * NUM_AA + b1.w];
            out4[t1] = o;
        }
        if (!v0) break;
    }

    // ---- Tail (n not divisible by 4; none for 2^23 but stay correct) ----
    for (int t = n4 * 4 + blockIdx.x * blockDim.x + tid; t < n; t += stride)
        out[t] = s_lut[ii[t] * NUM_AA + jj[t]];
}

extern "C" void kernel_launch(void* const* d_in, const int* in_sizes, int n_in,
                              void* d_out, int out_size) {
    const float* features = (const float*)d_in[0];
    const float* M        = (const float*)d_in[1];
    const int*   idx_i    = (const int*)d_in[2];
    const int*   idx_j    = (const int*)d_in[3];
    float*       out      = (float*)d_out;

    int n  = in_sizes[2];
    int n4 = n / 4;

    // 148 SMs x 8 CTAs of 256 threads (32 regs, ~5.2 KB smem -> fits 8/SM).
    int blocks = 148 * 8;
    // Never launch more blocks than there is work for (tiny-n safety).
    int maxNeeded = (n4 > 0 ? (n4 + 511) / 512 : 1);
    if (blocks > maxNeeded && maxNeeded > 0) blocks = maxNeeded;

    snack_fused<<<blocks, 256>>>(features, M,
                                 (const int4*)idx_i, (const int4*)idx_j,
                                 (float4*)out, n4,
                                 idx_i, idx_j, out, n);
}